// round 11
// baseline (speedup 1.0000x reference)
#include <cuda_runtime.h>
#include <math_constants.h>

#define NB   8
#define NC   3
#define NN   4096
#define KK   10
#define TPB  480          // threads per block (2 per query)
#define QPB  240          // queries per block
#define NBB  18           // blocks per batch (17*240 + 16 = 4096)
#define MLP0 64
#define MLP1 64
#define BUFN 48           // u32 mask-entries per thread
#define WPAD 40           // padded wfold row: 10 x float4 (x,y,z,0)

// dynamic smem layout:
//   float4 cand[4096]        : 65536 B
//   float  w1eff[64*30]      :  7680 B
//   float  wfold[64*40]      : 10240 B
//   float  biasf[64]         :   256 B
//   u32    buf[BUFN][TPB]    : 92160 B
#define SMEM_FLOATS (NN*4 + MLP0*30 + MLP1*WPAD + MLP1)
#define SMEM_BYTES  (SMEM_FLOATS*4 + BUFN*TPB*4)

// exact sorted insert (strict <, caller guarantees v < d[KK-1])
__device__ __forceinline__ void insert10(float (&d)[KK], int (&ix)[KK],
                                         float v, int m)
{
    bool c_hi = true;
    #pragma unroll
    for (int i = KK - 1; i >= 1; --i) {
        bool c_lo = v < d[i - 1];
        float tn = c_hi ? v : d[i];
        int   ti = c_hi ? m : ix[i];
        d[i]  = c_lo ? d[i - 1]  : tn;
        ix[i] = c_lo ? ix[i - 1] : ti;
        c_hi = c_lo;
    }
    d[0]  = c_hi ? v : d[0];
    ix[0] = c_hi ? m : ix[0];
}

__global__ __launch_bounds__(TPB, 1)
void pcms_kernel(const float* __restrict__ pos,
                 const float* __restrict__ w1,
                 const float* __restrict__ b1,
                 const float* __restrict__ w2,
                 const float* __restrict__ b2,
                 float* __restrict__ out)
{
    extern __shared__ float smem[];
    float4*   cand  = reinterpret_cast<float4*>(smem);
    float*    w1eff = smem + NN * 4;
    float*    wfold = w1eff + MLP0 * 30;
    float*    biasf = wfold + MLP1 * WPAD;
    unsigned* buf   = reinterpret_cast<unsigned*>(smem + SMEM_FLOATS);

    const int tid = threadIdx.x;
    const int b   = blockIdx.x / NBB;
    const int n0  = (blockIdx.x % NBB) * QPB;

    // ---- stage 0a: candidate table (x, y, z, 0.5*|p|^2) ----
    const float* pb = pos + b * (NC * NN);
    for (int n = tid; n < NN; n += TPB) {
        float x = pb[n];
        float y = pb[NN + n];
        float z = pb[2 * NN + n];
        cand[n] = make_float4(x, y, z, 0.5f * (x * x + y * y + z * z));
    }

    // ---- stage 0b: fold w1 over the INDS/squeeze mapping -> w1eff[o][r*3+c] ----
    if (tid < MLP0) {
        float acc[30];
        #pragma unroll
        for (int i = 0; i < 30; ++i) acc[i] = 0.f;
        const int STAB[4][2][2] = {
            {{0, 2}, {4, 6}},   // a
            {{3, 5}, {7, 9}},   // d
            {{1, 3}, {5, 7}},   // b
            {{2, 4}, {6, 8}}    // c
        };
        #pragma unroll
        for (int q = 0; q < 4; ++q)
            #pragma unroll
            for (int c = 0; c < 3; ++c)
                #pragma unroll
                for (int i = 0; i < 2; ++i)
                    #pragma unroll
                    for (int j = 0; j < 2; ++j)
                        acc[STAB[q][i][j] * 3 + c] +=
                            w1[tid * 48 + (q * 3 + c) * 4 + i * 2 + j];
        #pragma unroll
        for (int i = 0; i < 30; ++i) w1eff[tid * 30 + i] = acc[i];
    }
    __syncthreads();

    // ---- stage 0c: wfold[p][r*4+c] (padded float4 rows) + bias fold ----
    for (int e = tid; e < MLP1 * WPAD; e += TPB) {
        int p = e / WPAD, t = e % WPAD, r = t >> 2, c = t & 3;
        float s = 0.f;
        if (c < 3) {
            #pragma unroll 8
            for (int o = 0; o < MLP0; ++o)
                s = fmaf(w2[p * MLP0 + o], w1eff[o * 30 + r * 3 + c], s);
        }
        wfold[e] = s;
    }
    if (tid < MLP1) {
        float s = b2[tid];
        #pragma unroll 8
        for (int o = 0; o < MLP0; ++o) s = fmaf(w2[tid * MLP0 + o], b1[o], s);
        biasf[tid] = s;
    }
    __syncthreads();

    // ---- stage 1: exact 10-NN, lane-pair per query, mask-buffered accepts ----
    const int s  = tid & 1;            // slice
    const int nq = n0 + (tid >> 1);    // query index
    const bool valid = (nq < NN);      // warp-uniform (16-query granularity)

    if (valid) {
        const float4 qd = cand[nq];
        const float qx = qd.x, qy = qd.y, qz = qd.z;

        float dist[KK];
        int   idx[KK];
        #pragma unroll
        for (int i = 0; i < KK; ++i) { dist[i] = CUDART_INF_F; idx[i] = 0; }

        float kth = CUDART_INF_F;   // conservative bound on current 10th
        float k8  = CUDART_INF_F;

        unsigned* const bbase = buf + tid;
        unsigned* const blim  = bbase + (BUFN - 1) * TPB;
        unsigned* bptr = bbase;

        auto flush = [&]() {
            const int n = (int)((bptr - bbase) / TPB);
            int j = 0;
            while (__any_sync(0xffffffffu, j < n)) {
                unsigned en = (j < n) ? bbase[j * TPB] : 0u;
                unsigned mask = en >> 16;
                const int mbase = s + 32 * (int)(en & 0xffffu);
                while (mask) {                    // divergent, vote-free
                    int u = __ffs(mask) - 1;
                    mask &= mask - 1;
                    const int m = mbase + 2 * u;
                    float4 cc = cand[m];
                    float v = cc.w;               // bit-identical recompute
                    v = fmaf(-qx, cc.x, v);
                    v = fmaf(-qy, cc.y, v);
                    v = fmaf(-qz, cc.z, v);
                    if (v < dist[KK - 1]) insert10(dist, idx, v, m);
                }
                ++j;
            }
            bptr = bbase;
            kth  = dist[KK - 1];
            k8   = dist[KK - 2];
        };

        for (int k = 0; k < NN / 32; ++k) {       // 16 candidates per block
            const int m0 = s + 32 * k;
            float e[16];
            #pragma unroll
            for (int u = 0; u < 16; ++u) {
                float4 cc = cand[m0 + 2 * u];
                float t = cc.w;
                t = fmaf(-qx, cc.x, t);
                t = fmaf(-qy, cc.y, t);
                e[u] = fmaf(-qz, cc.z, t);
            }
            unsigned mask = 0;
            #pragma unroll
            for (int u = 0; u < 16; ++u) {
                if (e[u] < kth) {                 // @P LOP3 + @P FMAX only
                    mask |= (1u << u);
                    kth = fmaxf(k8, e[u]);        // stays >= true current 10th
                }
            }
            if (mask) {                           // <=1 entry per block
                *bptr = (mask << 16) | (unsigned)k;
                bptr += TPB;
            }
            if (__any_sync(0xffffffffu, bptr >= blim)) flush();
        }
        flush();

        // ---- stage 1b: symmetric pair-merge ((v, idx) lexicographic) ----
        {
            float pd[KK]; int pi[KK];
            #pragma unroll
            for (int r = 0; r < KK; ++r) {
                pd[r] = __shfl_xor_sync(0xffffffffu, dist[r], 1);
                pi[r] = __shfl_xor_sync(0xffffffffu, idx[r], 1);
            }
            #pragma unroll
            for (int r = 0; r < KK; ++r) {
                const float v = pd[r];
                const int  mi = pi[r];
                bool c_hi = (v < dist[KK - 1]) ||
                            (v == dist[KK - 1] && mi < idx[KK - 1]);
                #pragma unroll
                for (int i = KK - 1; i >= 1; --i) {
                    bool c_lo = (v < dist[i - 1]) ||
                                (v == dist[i - 1] && mi < idx[i - 1]);
                    float tn = c_hi ? v : dist[i];
                    int   ti = c_hi ? mi : idx[i];
                    dist[i] = c_lo ? dist[i - 1] : tn;
                    idx[i]  = c_lo ? idx[i - 1]  : ti;
                    c_hi = c_lo;
                }
                dist[0] = c_hi ? v : dist[0];
                idx[0]  = c_hi ? mi : idx[0];
            }
        }

        // ---- stage 2: gather neighbors + folded matvec (float4 weights) ----
        float nx[KK], ny[KK], nz[KK];
        #pragma unroll
        for (int r = 0; r < KK; ++r) {
            float4 cc = cand[idx[r]];
            nx[r] = cc.x; ny[r] = cc.y; nz[r] = cc.z;
        }

        const int p0 = s * (MLP1 / 2);
        float* op = out + b * (MLP1 * NN) + nq;
        #pragma unroll 4
        for (int pj = 0; pj < MLP1 / 2; ++pj) {
            const int p = p0 + pj;
            float acc = biasf[p];
            const float4* wf4 = reinterpret_cast<const float4*>(wfold + p * WPAD);
            #pragma unroll
            for (int r = 0; r < KK; ++r) {
                float4 w = wf4[r];
                acc = fmaf(w.x, nx[r], acc);
                acc = fmaf(w.y, ny[r], acc);
                acc = fmaf(w.z, nz[r], acc);
            }
            op[p * NN] = acc;
        }
    }
}

extern "C" void kernel_launch(void* const* d_in, const int* in_sizes, int n_in,
                              void* d_out, int out_size)
{
    const float* pos = (const float*)d_in[0];   // (8, 3, 4096)
    const float* w1  = (const float*)d_in[1];   // (64, 12, 2, 2)
    const float* b1  = (const float*)d_in[2];   // (64,)
    const float* w2  = (const float*)d_in[3];   // (64, 64)
    const float* b2  = (const float*)d_in[4];   // (64,)
    float* out = (float*)d_out;                 // (8, 64, 4096)

    cudaFuncSetAttribute(pcms_kernel, cudaFuncAttributeMaxDynamicSharedMemorySize, SMEM_BYTES);

    dim3 grid(NB * NBB);   // 144 blocks
    dim3 block(TPB);
    pcms_kernel<<<grid, block, SMEM_BYTES>>>(pos, w1, b1, w2, b2, out);
}

// round 12
// speedup vs baseline: 1.7159x; 1.7159x over previous
#include <cuda_runtime.h>
#include <math_constants.h>

#define NB   8
#define NC   3
#define NN   4096
#define KK   10
#define TPB  480          // threads per block (2 per query)
#define QPB  240          // queries per block
#define NBB  18           // blocks per batch (17*240 + 16 = 4096)
#define MLP0 64
#define MLP1 64
#define BUFN 24           // u64 accept entries per thread
#define WPAD 40           // padded wfold row: 10 x float4 (x,y,z,0)

// dynamic smem layout:
//   float4 cand[4096]        : 65536 B
//   float  w1eff[64*30]      :  7680 B
//   float  wfold[64*40]      : 10240 B
//   float  biasf[64]         :   256 B
//   u64    buf[BUFN][TPB]    : 92160 B
#define SMEM_FLOATS (NN*4 + MLP0*30 + MLP1*WPAD + MLP1)
#define SMEM_BYTES  (SMEM_FLOATS*4 + BUFN*TPB*8)

__global__ __launch_bounds__(TPB, 1)
void pcms_kernel(const float* __restrict__ pos,
                 const float* __restrict__ w1,
                 const float* __restrict__ b1,
                 const float* __restrict__ w2,
                 const float* __restrict__ b2,
                 float* __restrict__ out)
{
    extern __shared__ float smem[];
    float4* cand  = reinterpret_cast<float4*>(smem);
    float*  w1eff = smem + NN * 4;
    float*  wfold = w1eff + MLP0 * 30;
    float*  biasf = wfold + MLP1 * WPAD;
    unsigned long long* buf =
        reinterpret_cast<unsigned long long*>(smem + SMEM_FLOATS);

    const int tid = threadIdx.x;
    const int b   = blockIdx.x / NBB;
    const int n0  = (blockIdx.x % NBB) * QPB;

    // ---- stage 0a: candidate table (x, y, z, 0.5*|p|^2) ----
    const float* pb = pos + b * (NC * NN);
    for (int n = tid; n < NN; n += TPB) {
        float x = pb[n];
        float y = pb[NN + n];
        float z = pb[2 * NN + n];
        cand[n] = make_float4(x, y, z, 0.5f * (x * x + y * y + z * z));
    }

    // ---- stage 0b: fold w1 over the INDS/squeeze mapping -> w1eff[o][r*3+c] ----
    if (tid < MLP0) {
        float acc[30];
        #pragma unroll
        for (int i = 0; i < 30; ++i) acc[i] = 0.f;
        const int STAB[4][2][2] = {
            {{0, 2}, {4, 6}},   // a
            {{3, 5}, {7, 9}},   // d
            {{1, 3}, {5, 7}},   // b
            {{2, 4}, {6, 8}}    // c
        };
        #pragma unroll
        for (int q = 0; q < 4; ++q)
            #pragma unroll
            for (int c = 0; c < 3; ++c)
                #pragma unroll
                for (int i = 0; i < 2; ++i)
                    #pragma unroll
                    for (int j = 0; j < 2; ++j) {
                        int r = STAB[q][i][j];
                        acc[r * 3 + c] += w1[tid * 48 + (q * 3 + c) * 4 + i * 2 + j];
                    }
        #pragma unroll
        for (int i = 0; i < 30; ++i) w1eff[tid * 30 + i] = acc[i];
    }
    __syncthreads();

    // ---- stage 0c: wfold[p][r*4+c] (padded float4 rows) + bias fold ----
    for (int e = tid; e < MLP1 * WPAD; e += TPB) {
        int p = e / WPAD, t = e % WPAD, r = t >> 2, c = t & 3;
        float s = 0.f;
        if (c < 3) {
            #pragma unroll 8
            for (int o = 0; o < MLP0; ++o)
                s = fmaf(w2[p * MLP0 + o], w1eff[o * 30 + r * 3 + c], s);
        }
        wfold[e] = s;
    }
    if (tid < MLP1) {
        float s = b2[tid];
        #pragma unroll 8
        for (int o = 0; o < MLP0; ++o) s = fmaf(w2[tid * MLP0 + o], b1[o], s);
        biasf[tid] = s;
    }
    __syncthreads();

    // ---- stage 1: exact 10-NN, lane-pair per query, buffered accepts ----
    const int s  = tid & 1;            // slice
    const int nq = n0 + (tid >> 1);    // query index
    if (nq >= NN) return;              // tail guard (warp-uniform, after syncs)

    const float4 qd = cand[nq];
    const float qx = qd.x, qy = qd.y, qz = qd.z;

    float dist[KK];
    int   idx[KK];
    #pragma unroll
    for (int i = 0; i < KK; ++i) { dist[i] = CUDART_INF_F; idx[i] = 0; }

    // live conservative thresholds: kth >= true dist[9], k8 >= true dist[8]
    float kth = CUDART_INF_F;
    float k8  = CUDART_INF_F;

    unsigned long long* const bbase = buf + tid;
    unsigned long long* const blim  = bbase + (BUFN - 16) * TPB;  // flush-if point
    unsigned long long* bptr = bbase;

    auto flush = [&]() {
        const int n = (int)((bptr - bbase) / TPB);
        int j = 0;
        while (__any_sync(0xffffffffu, j < n)) {
            if (j < n) {
                unsigned long long pk = bbase[j * TPB];
                const float v = __int_as_float((int)(pk >> 32));
                const int   m = (int)(pk & 0xffffffffu);
                if (v < dist[KK - 1]) {            // live re-gate (exact)
                    bool c_hi = true;
                    #pragma unroll
                    for (int i = KK - 1; i >= 1; --i) {
                        bool c_lo = v < dist[i - 1];
                        float tn = c_hi ? v : dist[i];
                        int   ti = c_hi ? m : idx[i];
                        dist[i] = c_lo ? dist[i - 1] : tn;
                        idx[i]  = c_lo ? idx[i - 1]  : ti;
                        c_hi = c_lo;
                    }
                    dist[0] = c_hi ? v : dist[0];
                    idx[0]  = c_hi ? m : idx[0];
                }
            }
            ++j;
        }
        bptr = bbase;
        kth  = dist[KK - 1];
        k8   = dist[KK - 2];
    };

    for (int m0 = s; m0 < NN; m0 += 32) {
        float e[16];
        #pragma unroll
        for (int u = 0; u < 16; ++u) {
            float4 cc = cand[m0 + 2 * u];
            float t = cc.w;
            t = fmaf(-qx, cc.x, t);
            t = fmaf(-qy, cc.y, t);
            e[u] = fmaf(-qz, cc.z, t);
        }
        // predicated push + live threshold tightening (exact-conservative):
        // after accepting v, the true 10th is <= max(d8, v) and d8 only
        // decreases, so kth = max(k8, v) remains a valid upper bound.
        #pragma unroll
        for (int u = 0; u < 16; ++u) {
            if (e[u] < kth) {
                *bptr = (((unsigned long long)(unsigned)__float_as_int(e[u])) << 32)
                        | (unsigned)(m0 + 2 * u);
                bptr += TPB;
                kth = fmaxf(k8, e[u]);
            }
        }
        // room check once per 16 candidates (need 16 free slots next block)
        if (__any_sync(0xffffffffu, bptr >= blim)) flush();
    }
    flush();   // drain remainder

    // ---- stage 1b: symmetric pair-merge (snapshot partner, then insert) ----
    float pd[KK]; int pi[KK];
    #pragma unroll
    for (int r = 0; r < KK; ++r) {
        pd[r] = __shfl_xor_sync(0xffffffffu, dist[r], 1);
        pi[r] = __shfl_xor_sync(0xffffffffu, idx[r], 1);
    }
    #pragma unroll
    for (int r = 0; r < KK; ++r) {
        const float v  = pd[r];
        const int   mi = pi[r];
        bool c_hi = (v < dist[KK - 1]) || (v == dist[KK - 1] && mi < idx[KK - 1]);
        #pragma unroll
        for (int i = KK - 1; i >= 1; --i) {
            bool c_lo = (v < dist[i - 1]) || (v == dist[i - 1] && mi < idx[i - 1]);
            float tn = c_hi ? v : dist[i];
            int   ti = c_hi ? mi : idx[i];
            dist[i] = c_lo ? dist[i - 1] : tn;
            idx[i]  = c_lo ? idx[i - 1]  : ti;
            c_hi = c_lo;
        }
        dist[0] = c_hi ? v : dist[0];
        idx[0]  = c_hi ? mi : idx[0];
    }

    // ---- stage 2: gather neighbors + folded matvec (float4 weights) ----
    float nx[KK], ny[KK], nz[KK];
    #pragma unroll
    for (int r = 0; r < KK; ++r) {
        float4 cc = cand[idx[r]];
        nx[r] = cc.x; ny[r] = cc.y; nz[r] = cc.z;
    }

    const int p0 = s * (MLP1 / 2);
    float* op = out + b * (MLP1 * NN) + nq;
    #pragma unroll 4
    for (int pj = 0; pj < MLP1 / 2; ++pj) {
        const int p = p0 + pj;
        float acc = biasf[p];
        const float4* wf4 = reinterpret_cast<const float4*>(wfold + p * WPAD);
        #pragma unroll
        for (int r = 0; r < KK; ++r) {
            float4 w = wf4[r];
            acc = fmaf(w.x, nx[r], acc);
            acc = fmaf(w.y, ny[r], acc);
            acc = fmaf(w.z, nz[r], acc);
        }
        op[p * NN] = acc;
    }
}

extern "C" void kernel_launch(void* const* d_in, const int* in_sizes, int n_in,
                              void* d_out, int out_size)
{
    const float* pos = (const float*)d_in[0];   // (8, 3, 4096)
    const float* w1  = (const float*)d_in[1];   // (64, 12, 2, 2)
    const float* b1  = (const float*)d_in[2];   // (64,)
    const float* w2  = (const float*)d_in[3];   // (64, 64)
    const float* b2  = (const float*)d_in[4];   // (64,)
    float* out = (float*)d_out;                 // (8, 64, 4096)

    cudaFuncSetAttribute(pcms_kernel, cudaFuncAttributeMaxDynamicSharedMemorySize, SMEM_BYTES);

    dim3 grid(NB * NBB);   // 144 blocks
    dim3 block(TPB);
    pcms_kernel<<<grid, block, SMEM_BYTES>>>(pos, w1, b1, w2, b2, out);
}